// round 7
// baseline (speedup 1.0000x reference)
#include <cuda_runtime.h>

// Problem constants: B=4, M=8, N=128, D=32, 2D=64, H=64. BM = B*M = 32 sets.
#define NSET 32
#define NN   128
#define DD   32
#define DD2  64

// Padded strides: 17 float4 = 272 B row stride => 4-bank skew, conflict-free.
#define A1S_STRIDE4 17
#define DS_STRIDE   68

typedef unsigned long long u64;

// Scratch (device globals -- no allocation allowed)
__device__ float g_x1[NSET * NN * DD];
__device__ float g_A1[NSET * NN * DD2];
__device__ float g_A2[NSET * NN * DD2];
__device__ float g_mask[NSET * NN];

// ---------------- packed f32x2 helpers (sm_103a) ----------------
__device__ __forceinline__ u64 f2add(u64 a, u64 b) {
    u64 r; asm("add.rn.f32x2 %0,%1,%2;" : "=l"(r) : "l"(a), "l"(b)); return r;
}
__device__ __forceinline__ u64 f2mul(u64 a, u64 b) {
    u64 r; asm("mul.rn.f32x2 %0,%1,%2;" : "=l"(r) : "l"(a), "l"(b)); return r;
}
__device__ __forceinline__ u64 f2fma(u64 a, u64 b, u64 c) {
    u64 r; asm("fma.rn.f32x2 %0,%1,%2,%3;" : "=l"(r) : "l"(a), "l"(b), "l"(c)); return r;
}
__device__ __forceinline__ u64 f2pack(float lo, float hi) {
    u64 r; asm("mov.b64 %0,{%1,%2};" : "=l"(r) : "f"(lo), "f"(hi)); return r;
}
__device__ __forceinline__ void f2unpack(float& lo, float& hi, u64 v) {
    asm("mov.b64 {%0,%1},%2;" : "=f"(lo), "=f"(hi) : "l"(v));
}
__device__ __forceinline__ float tanh_ap(float x) {
    float r; asm("tanh.approx.f32 %0,%1;" : "=f"(r) : "f"(x)); return r;
}

// scalar gelu (jax tanh form) via tanh.approx.
__device__ __forceinline__ float gelu_f(float t) {
    float u  = t * t;
    float z  = t * fmaf(0.0356774081f, u, 0.7978845608f);
    float th = tanh_ap(z);
    float ht = 0.5f * t;
    return fmaf(th, ht, ht);
}

// packed: acc += gelu(a+d) * v on 2 lanes.
__device__ __forceinline__ u64 gelu2_acc(u64 a, u64 d, u64 v, u64 acc,
                                         u64 C1, u64 C2, u64 HF) {
    u64 t = f2add(a, d);
    u64 u = f2mul(t, t);
    u64 p = f2fma(C1, u, C2);
    u64 z = f2mul(t, p);
    float zl, zh; f2unpack(zl, zh, z);
    u64 th = f2pack(tanh_ap(zl), tanh_ap(zh));
    u64 ht = f2mul(t, HF);
    u64 g  = f2fma(th, ht, ht);
    return f2fma(g, v, acc);
}

// ---------------------------------------------------------------------------
// Kernel 1: per-set norm stats + set_norm + MLP1 + A1/A2 precompute.
// grid = NSET * 8 blocks (one set x 16 rows each), 256 threads.
// ---------------------------------------------------------------------------
__global__ __launch_bounds__(256) void k1(
    const float* __restrict__ x, const float* __restrict__ x_size,
    const float* __restrict__ W1a, const float* __restrict__ b1a,
    const float* __restrict__ W1b, const float* __restrict__ b1b,
    const float* __restrict__ W2a)
{
    __shared__ float xs[NN * DD];
    __shared__ float w1a[DD * DD2];
    __shared__ float w1b[DD2 * DD];
    __shared__ float w2a[DD * DD2];
    __shared__ float xn[16 * DD];
    __shared__ float maskS[NN];
    __shared__ float red[8];
    __shared__ float statS[2];

    const int bm   = blockIdx.x >> 3;
    const int tile = blockIdx.x & 7;
    const int r0   = tile * 16;
    const int tid  = threadIdx.x;

    const float4* xg  = (const float4*)(x + bm * (NN * DD));
    float4*       xs4 = (float4*)xs;
    float lsum = 0.f;
    #pragma unroll
    for (int i = tid; i < 1024; i += 256) {
        float4 v = xg[i];
        xs4[i] = v;
        lsum += v.x + v.y + v.z + v.w;
    }
    #pragma unroll
    for (int i = tid; i < 512; i += 256) ((float4*)w1a)[i] = ((const float4*)W1a)[i];
    #pragma unroll
    for (int i = tid; i < 512; i += 256) ((float4*)w1b)[i] = ((const float4*)W1b)[i];
    #pragma unroll
    for (int i = tid; i < 512; i += 256) ((float4*)w2a)[i] = ((const float4*)W2a)[i];
    __syncthreads();

    if (tid < NN) {
        const float* row = xs + tid * DD;
        float m = 0.f;
        #pragma unroll
        for (int e = 0; e < DD; e++) if (row[e] != 0.f) { m = 1.f; break; }
        maskS[tid] = m;
    }
    #pragma unroll
    for (int o = 16; o; o >>= 1) lsum += __shfl_xor_sync(0xffffffffu, lsum, o);
    if ((tid & 31) == 0) red[tid >> 5] = lsum;
    __syncthreads();
    const float denom = x_size[bm >> 3] * (float)DD;
    if (tid == 0) {
        float s = 0.f;
        #pragma unroll
        for (int w = 0; w < 8; w++) s += red[w];
        statS[0] = s / denom;
    }
    __syncthreads();
    const float mean = statS[0];

    float lss = 0.f;
    #pragma unroll
    for (int i = tid; i < 1024; i += 256) {
        float4 v = xs4[i];
        float m = maskS[i >> 3];
        float a = v.x - mean, b = v.y - mean, c = v.z - mean, d = v.w - mean;
        lss += (a * a + b * b + c * c + d * d) * m;
    }
    #pragma unroll
    for (int o = 16; o; o >>= 1) lss += __shfl_xor_sync(0xffffffffu, lss, o);
    if ((tid & 31) == 0) red[tid >> 5] = lss;
    __syncthreads();
    if (tid == 0) {
        float s = 0.f;
        #pragma unroll
        for (int w = 0; w < 8; w++) s += red[w];
        statS[1] = 1.0f / (sqrtf(s / denom) + 1e-8f);
    }
    __syncthreads();
    const float inv = statS[1];

    #pragma unroll
    for (int i = tid; i < 512; i += 256) {
        int n = r0 + (i >> 5);
        int e = i & 31;
        xn[i] = (xs[n * DD + e] - mean) * inv * maskS[n];
    }
    if (tid < 16) g_mask[bm * NN + r0 + tid] = maskS[r0 + tid];
    __syncthreads();

    float* hb  = xs;          // 16*64
    float* x1b = xs + 1024;   // 16*32

    #pragma unroll
    for (int i = tid; i < 1024; i += 256) {
        int n = i >> 6, k = i & 63;
        float acc = b1a[k];
        #pragma unroll
        for (int e = 0; e < DD; e++) acc = fmaf(xn[n * DD + e], w1a[e * DD2 + k], acc);
        hb[i] = gelu_f(acc);
    }
    __syncthreads();

    #pragma unroll
    for (int i = tid; i < 512; i += 256) {
        int n = i >> 5, d = i & 31;
        float acc = b1b[d];
        #pragma unroll
        for (int k = 0; k < DD2; k++) acc = fmaf(hb[n * DD2 + k], w1b[k * DD + d], acc);
        acc *= maskS[r0 + n];
        x1b[i] = acc;
        g_x1[bm * (NN * DD) + (r0 + n) * DD + d] = acc;
    }
    __syncthreads();

    #pragma unroll
    for (int i = tid; i < 1024; i += 256) {
        int n = i >> 6, k = i & 63;
        float a1 = 0.f, a2 = 0.f;
        #pragma unroll
        for (int e = 0; e < DD; e++) {
            float w = w2a[e * DD2 + k];
            a1 = fmaf(x1b[n * DD + e], w, a1);
            a2 = fmaf(xn[n * DD + e], w, a2);
        }
        g_A1[bm * (NN * DD2) + (r0 + n) * DD2 + k] = a1;
        g_A2[bm * (NN * DD2) + (r0 + n) * DD2 + k] = a2;
    }
}

// ---------------------------------------------------------------------------
// Kernel 2: pair scores via packed f32x2 + tanh.approx; then aggregation.
// grid = NSET * 32 blocks (one set x 4 j's), 256 threads, <=51 regs,
// 5 CTAs/SM -> 40 warps/SM for latency hiding.
// ---------------------------------------------------------------------------
__global__ __launch_bounds__(256, 5) void k2(
    const float* __restrict__ x,
    const float* __restrict__ b2a, const float* __restrict__ W2b,
    const float* __restrict__ b2b, const float* __restrict__ w3,
    const float* __restrict__ b3, float* __restrict__ out)
{
    __shared__ float A1s[NN * A1S_STRIDE4 * 4];   // padded rows, 34.8 KB
    __shared__ float dS[4 * DS_STRIDE];           // b2a[k] - A2[j0+j][k]
    __shared__ float vS[DD2];                     // W2b @ w3
    __shared__ float sS[NN * 4];                  // pair scores
    __shared__ float part[256];                   // aggregation partials
    __shared__ float cS;                          // b2b . w3

    const int bm = blockIdx.x >> 5;
    const int jt = blockIdx.x & 31;
    const int j0 = jt * 4;
    const int tid = threadIdx.x;

    // --- stage A1 (padded rows), dS, v, c ---
    const float4* a1g  = (const float4*)(g_A1 + bm * (NN * DD2));
    float4*       A1s4 = (float4*)A1s;
    #pragma unroll
    for (int idx = tid; idx < 2048; idx += 256) {
        int i  = idx >> 4;
        int k4 = idx & 15;
        A1s4[i * A1S_STRIDE4 + k4] = a1g[idx];
    }
    {
        int jj = tid >> 6, k = tid & 63;    // 256 threads cover 4 x 64
        dS[jj * DS_STRIDE + k] = b2a[k] - g_A2[bm * (NN * DD2) + (j0 + jj) * DD2 + k];
    }
    if (tid >= 192) {
        int kk = tid - 192;
        float acc = 0.f;
        #pragma unroll
        for (int h = 0; h < 64; h++) acc = fmaf(W2b[kk * 64 + h], w3[h], acc);
        vS[kk] = acc;
    }
    if (tid == 0) {
        float acc = 0.f;
        #pragma unroll
        for (int h = 0; h < 64; h++) acc = fmaf(b2b[h], w3[h], acc);
        cS = acc;
    }
    __syncthreads();

    // --- pair phase: thread owns j = tid&3 and 2 i's (bi, bi+64) ---
    const int j  = tid & 3;
    const int bi = tid >> 2;     // 0..63
    const ulonglong2* A1s2 = (const ulonglong2*)A1s;
    const ulonglong2* dj2  = (const ulonglong2*)(dS + j * DS_STRIDE);
    const ulonglong2* vv2  = (const ulonglong2*)vS;

    const u64 C1 = f2pack(0.0356774081f, 0.0356774081f);
    const u64 C2 = f2pack(0.7978845608f, 0.7978845608f);
    const u64 HF = f2pack(0.5f, 0.5f);
    const u64 Z  = f2pack(0.f, 0.f);
    const u64 CI = f2pack(cS, 0.f);   // fold bias into accumulator

    u64 a0a = CI, a0b = Z, a1a = CI, a1b = Z;
    #pragma unroll
    for (int k4 = 0; k4 < 16; k4++) {
        ulonglong2 dd = dj2[k4];
        ulonglong2 vv = vv2[k4];
        ulonglong2 q0 = A1s2[bi * A1S_STRIDE4 + k4];
        ulonglong2 q1 = A1s2[(bi + 64) * A1S_STRIDE4 + k4];
        a0a = gelu2_acc(q0.x, dd.x, vv.x, a0a, C1, C2, HF);
        a0b = gelu2_acc(q0.y, dd.y, vv.y, a0b, C1, C2, HF);
        a1a = gelu2_acc(q1.x, dd.x, vv.x, a1a, C1, C2, HF);
        a1b = gelu2_acc(q1.y, dd.y, vv.y, a1b, C1, C2, HF);
    }
    {
        float l0, h0, l1, h1;
        u64 s0p = f2add(a0a, a0b);
        u64 s1p = f2add(a1a, a1b);
        f2unpack(l0, h0, s0p);
        f2unpack(l1, h1, s1p);
        sS[(bi     ) * 4 + j] = l0 + h0;
        sS[(bi + 64) * 4 + j] = l1 + h1;
    }
    __syncthreads();

    // --- aggregation: out[j,d] = sum_i s[i,j]*x1[i,d] + b3 + residual, masked.
    // 256 threads: each (j,d) handled by 2 threads, one per i-half. ---
    {
        const int jd   = tid & 127;
        const int half = tid >> 7;
        const int jj   = jd >> 5;         // 0..3
        const int d    = jd & 31;
        const float* x1p = g_x1 + bm * (NN * DD) + d;
        const float* sp  = sS + jj;
        const int ib = half * 64;
        float acc = 0.f;
        #pragma unroll 8
        for (int i = ib; i < ib + 64; i++) acc = fmaf(sp[i * 4], x1p[i * DD], acc);
        part[tid] = acc;
    }
    __syncthreads();
    if (tid < 128) {
        const int jj = tid >> 5;
        const int d  = tid & 31;
        const int gj = j0 + jj;
        const int gidx = bm * (NN * DD) + gj * DD + d;
        float r = part[tid] + part[tid + 128];
        out[gidx] = (r + b3[0] + x[gidx]) * g_mask[bm * NN + gj];
    }
}

// ---------------------------------------------------------------------------
extern "C" void kernel_launch(void* const* d_in, const int* in_sizes, int n_in,
                              void* d_out, int out_size)
{
    (void)in_sizes; (void)n_in; (void)out_size;
    const float* x    = (const float*)d_in[0];
    const float* xsz  = (const float*)d_in[1];
    const float* W1a  = (const float*)d_in[2];
    const float* b1a  = (const float*)d_in[3];
    const float* W1b  = (const float*)d_in[4];
    const float* b1b  = (const float*)d_in[5];
    const float* W2a  = (const float*)d_in[6];
    const float* b2a  = (const float*)d_in[7];
    const float* W2b  = (const float*)d_in[8];
    const float* b2b  = (const float*)d_in[9];
    const float* w3   = (const float*)d_in[10];
    const float* b3   = (const float*)d_in[11];
    float* out = (float*)d_out;

    k1<<<NSET * 8, 256>>>(x, xsz, W1a, b1a, W1b, b1b, W2a);
    k2<<<NSET * 32, 256>>>(x, b2a, W2b, b2b, w3, b3, out);
}

// round 8
// speedup vs baseline: 1.2613x; 1.2613x over previous
#include <cuda_runtime.h>

// Problem constants: B=4, M=8, N=128, D=32, 2D=64, H=64. BM = B*M = 32 sets.
#define NSET 32
#define NN   128
#define DD   32
#define DD2  64

// Padded strides: 17 float4 = 272 B row stride => 4-bank skew, conflict-free.
#define A1S_STRIDE4 17
#define DS_STRIDE   68

typedef unsigned long long u64;

// Scratch (device globals -- no allocation allowed)
__device__ float g_x1[NSET * NN * DD];
__device__ float g_A1[NSET * NN * DD2];
__device__ float g_A2[NSET * NN * DD2];
__device__ float g_mask[NSET * NN];

// ---------------- packed f32x2 helpers (sm_103a) ----------------
__device__ __forceinline__ u64 f2add(u64 a, u64 b) {
    u64 r; asm("add.rn.f32x2 %0,%1,%2;" : "=l"(r) : "l"(a), "l"(b)); return r;
}
__device__ __forceinline__ u64 f2mul(u64 a, u64 b) {
    u64 r; asm("mul.rn.f32x2 %0,%1,%2;" : "=l"(r) : "l"(a), "l"(b)); return r;
}
__device__ __forceinline__ u64 f2fma(u64 a, u64 b, u64 c) {
    u64 r; asm("fma.rn.f32x2 %0,%1,%2,%3;" : "=l"(r) : "l"(a), "l"(b), "l"(c)); return r;
}
__device__ __forceinline__ u64 f2pack(float lo, float hi) {
    u64 r; asm("mov.b64 %0,{%1,%2};" : "=l"(r) : "f"(lo), "f"(hi)); return r;
}
__device__ __forceinline__ void f2unpack(float& lo, float& hi, u64 v) {
    asm("mov.b64 {%0,%1},%2;" : "=f"(lo), "=f"(hi) : "l"(v));
}
__device__ __forceinline__ float tanh_ap(float x) {
    float r; asm("tanh.approx.f32 %0,%1;" : "=f"(r) : "f"(x)); return r;
}

// scalar gelu (jax tanh form) via tanh.approx.
__device__ __forceinline__ float gelu_f(float t) {
    float u  = t * t;
    float z  = t * fmaf(0.0356774081f, u, 0.7978845608f);
    float th = tanh_ap(z);
    float ht = 0.5f * t;
    return fmaf(th, ht, ht);
}

// packed: acc += gelu(a+d) * v on 2 lanes.
__device__ __forceinline__ u64 gelu2_acc(u64 a, u64 d, u64 v, u64 acc,
                                         u64 C1, u64 C2, u64 HF) {
    u64 t = f2add(a, d);
    u64 u = f2mul(t, t);
    u64 p = f2fma(C1, u, C2);
    u64 z = f2mul(t, p);
    float zl, zh; f2unpack(zl, zh, z);
    u64 th = f2pack(tanh_ap(zl), tanh_ap(zh));
    u64 ht = f2mul(t, HF);
    u64 g  = f2fma(th, ht, ht);
    return f2fma(g, v, acc);
}

// ---------------------------------------------------------------------------
// Kernel 1: per-set norm stats + set_norm + MLP1 + A1/A2 precompute.
// grid = NSET * 8 blocks (one set x 16 rows each), 256 threads.
// ---------------------------------------------------------------------------
__global__ __launch_bounds__(256) void k1(
    const float* __restrict__ x, const float* __restrict__ x_size,
    const float* __restrict__ W1a, const float* __restrict__ b1a,
    const float* __restrict__ W1b, const float* __restrict__ b1b,
    const float* __restrict__ W2a)
{
    __shared__ float xs[NN * DD];
    __shared__ float w1a[DD * DD2];
    __shared__ float w1b[DD2 * DD];
    __shared__ float w2a[DD * DD2];
    __shared__ float xn[16 * DD];
    __shared__ float maskS[NN];
    __shared__ float red[8];
    __shared__ float statS[2];

    const int bm   = blockIdx.x >> 3;
    const int tile = blockIdx.x & 7;
    const int r0   = tile * 16;
    const int tid  = threadIdx.x;

    const float4* xg  = (const float4*)(x + bm * (NN * DD));
    float4*       xs4 = (float4*)xs;
    float lsum = 0.f;
    #pragma unroll
    for (int i = tid; i < 1024; i += 256) {
        float4 v = xg[i];
        xs4[i] = v;
        lsum += v.x + v.y + v.z + v.w;
    }
    #pragma unroll
    for (int i = tid; i < 512; i += 256) ((float4*)w1a)[i] = ((const float4*)W1a)[i];
    #pragma unroll
    for (int i = tid; i < 512; i += 256) ((float4*)w1b)[i] = ((const float4*)W1b)[i];
    #pragma unroll
    for (int i = tid; i < 512; i += 256) ((float4*)w2a)[i] = ((const float4*)W2a)[i];
    __syncthreads();

    if (tid < NN) {
        const float* row = xs + tid * DD;
        float m = 0.f;
        #pragma unroll
        for (int e = 0; e < DD; e++) if (row[e] != 0.f) { m = 1.f; break; }
        maskS[tid] = m;
    }
    #pragma unroll
    for (int o = 16; o; o >>= 1) lsum += __shfl_xor_sync(0xffffffffu, lsum, o);
    if ((tid & 31) == 0) red[tid >> 5] = lsum;
    __syncthreads();
    const float denom = x_size[bm >> 3] * (float)DD;
    if (tid == 0) {
        float s = 0.f;
        #pragma unroll
        for (int w = 0; w < 8; w++) s += red[w];
        statS[0] = s / denom;
    }
    __syncthreads();
    const float mean = statS[0];

    float lss = 0.f;
    #pragma unroll
    for (int i = tid; i < 1024; i += 256) {
        float4 v = xs4[i];
        float m = maskS[i >> 3];
        float a = v.x - mean, b = v.y - mean, c = v.z - mean, d = v.w - mean;
        lss += (a * a + b * b + c * c + d * d) * m;
    }
    #pragma unroll
    for (int o = 16; o; o >>= 1) lss += __shfl_xor_sync(0xffffffffu, lss, o);
    if ((tid & 31) == 0) red[tid >> 5] = lss;
    __syncthreads();
    if (tid == 0) {
        float s = 0.f;
        #pragma unroll
        for (int w = 0; w < 8; w++) s += red[w];
        statS[1] = 1.0f / (sqrtf(s / denom) + 1e-8f);
    }
    __syncthreads();
    const float inv = statS[1];

    #pragma unroll
    for (int i = tid; i < 512; i += 256) {
        int n = r0 + (i >> 5);
        int e = i & 31;
        xn[i] = (xs[n * DD + e] - mean) * inv * maskS[n];
    }
    if (tid < 16) g_mask[bm * NN + r0 + tid] = maskS[r0 + tid];
    __syncthreads();

    float* hb  = xs;          // 16*64
    float* x1b = xs + 1024;   // 16*32

    #pragma unroll
    for (int i = tid; i < 1024; i += 256) {
        int n = i >> 6, k = i & 63;
        float acc = b1a[k];
        #pragma unroll
        for (int e = 0; e < DD; e++) acc = fmaf(xn[n * DD + e], w1a[e * DD2 + k], acc);
        hb[i] = gelu_f(acc);
    }
    __syncthreads();

    #pragma unroll
    for (int i = tid; i < 512; i += 256) {
        int n = i >> 5, d = i & 31;
        float acc = b1b[d];
        #pragma unroll
        for (int k = 0; k < DD2; k++) acc = fmaf(hb[n * DD2 + k], w1b[k * DD + d], acc);
        acc *= maskS[r0 + n];
        x1b[i] = acc;
        g_x1[bm * (NN * DD) + (r0 + n) * DD + d] = acc;
    }
    __syncthreads();

    #pragma unroll
    for (int i = tid; i < 1024; i += 256) {
        int n = i >> 6, k = i & 63;
        float a1 = 0.f, a2 = 0.f;
        #pragma unroll
        for (int e = 0; e < DD; e++) {
            float w = w2a[e * DD2 + k];
            a1 = fmaf(x1b[n * DD + e], w, a1);
            a2 = fmaf(xn[n * DD + e], w, a2);
        }
        g_A1[bm * (NN * DD2) + (r0 + n) * DD2 + k] = a1;
        g_A2[bm * (NN * DD2) + (r0 + n) * DD2 + k] = a2;
    }
}

// ---------------------------------------------------------------------------
// Kernel 2: pair scores via packed f32x2 + tanh.approx; then aggregation.
// grid = NSET * 8 blocks (one set x 16 j's), 512 threads, 2 CTAs/SM.
// Thread owns j = tid&15 and 4 i's -> dd/vv LDS amortized over 32 elements.
// ---------------------------------------------------------------------------
__global__ __launch_bounds__(512, 2) void k2(
    const float* __restrict__ x,
    const float* __restrict__ b2a, const float* __restrict__ W2b,
    const float* __restrict__ b2b, const float* __restrict__ w3,
    const float* __restrict__ b3, float* __restrict__ out)
{
    __shared__ float A1s[NN * A1S_STRIDE4 * 4];   // padded rows, 34.8 KB
    __shared__ float dS[16 * DS_STRIDE];          // b2a[k] - A2[j0+j][k]
    __shared__ float vS[DD2];                     // W2b @ w3
    __shared__ float sS[NN * 16];                 // pair scores [i][j]
    __shared__ float cS;                          // b2b . w3

    const int bm = blockIdx.x >> 3;
    const int jt = blockIdx.x & 7;
    const int j0 = jt * 16;
    const int tid = threadIdx.x;

    // --- stage A1 (padded rows), dS, v, c ---
    const float4* a1g  = (const float4*)(g_A1 + bm * (NN * DD2));
    float4*       A1s4 = (float4*)A1s;
    #pragma unroll
    for (int idx = tid; idx < 2048; idx += 512) {
        int i  = idx >> 4;
        int k4 = idx & 15;
        A1s4[i * A1S_STRIDE4 + k4] = a1g[idx];
    }
    #pragma unroll
    for (int i = tid; i < 1024; i += 512) {
        int jj = i >> 6, k = i & 63;
        dS[jj * DS_STRIDE + k] = b2a[k] - g_A2[bm * (NN * DD2) + (j0 + jj) * DD2 + k];
    }
    if (tid >= 448) {
        int kk = tid - 448;
        float acc = 0.f;
        #pragma unroll
        for (int h = 0; h < 64; h++) acc = fmaf(W2b[kk * 64 + h], w3[h], acc);
        vS[kk] = acc;
    }
    if (tid == 0) {
        float acc = 0.f;
        #pragma unroll
        for (int h = 0; h < 64; h++) acc = fmaf(b2b[h], w3[h], acc);
        cS = acc;
    }
    __syncthreads();

    // --- pair phase: thread owns j = tid&15 and 4 i's (bi, +32, +64, +96) ---
    const int j  = tid & 15;
    const int bi = tid >> 4;     // 0..31
    const ulonglong2* A1s2 = (const ulonglong2*)A1s;
    const ulonglong2* dj2  = (const ulonglong2*)(dS + j * DS_STRIDE);
    const ulonglong2* vv2  = (const ulonglong2*)vS;

    const u64 C1 = f2pack(0.0356774081f, 0.0356774081f);
    const u64 C2 = f2pack(0.7978845608f, 0.7978845608f);
    const u64 HF = f2pack(0.5f, 0.5f);
    const u64 CI = f2pack(cS, 0.f);   // fold bias into accumulator

    u64 acc0 = CI, acc1 = CI, acc2 = CI, acc3 = CI;
    #pragma unroll
    for (int k4 = 0; k4 < 16; k4++) {
        ulonglong2 dd = dj2[k4];
        ulonglong2 vv = vv2[k4];
        ulonglong2 q;
        q = A1s2[bi * A1S_STRIDE4 + k4];
        acc0 = gelu2_acc(q.x, dd.x, vv.x, acc0, C1, C2, HF);
        acc0 = gelu2_acc(q.y, dd.y, vv.y, acc0, C1, C2, HF);
        q = A1s2[(bi + 32) * A1S_STRIDE4 + k4];
        acc1 = gelu2_acc(q.x, dd.x, vv.x, acc1, C1, C2, HF);
        acc1 = gelu2_acc(q.y, dd.y, vv.y, acc1, C1, C2, HF);
        q = A1s2[(bi + 64) * A1S_STRIDE4 + k4];
        acc2 = gelu2_acc(q.x, dd.x, vv.x, acc2, C1, C2, HF);
        acc2 = gelu2_acc(q.y, dd.y, vv.y, acc2, C1, C2, HF);
        q = A1s2[(bi + 96) * A1S_STRIDE4 + k4];
        acc3 = gelu2_acc(q.x, dd.x, vv.x, acc3, C1, C2, HF);
        acc3 = gelu2_acc(q.y, dd.y, vv.y, acc3, C1, C2, HF);
    }
    {
        float l, h;
        f2unpack(l, h, acc0); sS[(bi     ) * 16 + j] = l + h;
        f2unpack(l, h, acc1); sS[(bi + 32) * 16 + j] = l + h;
        f2unpack(l, h, acc2); sS[(bi + 64) * 16 + j] = l + h;
        f2unpack(l, h, acc3); sS[(bi + 96) * 16 + j] = l + h;
    }
    __syncthreads();

    // --- aggregation: out[j,d] = sum_i s[i,j]*x1[i,d] + b3 + residual, masked.
    // 512 threads = 16 j x 32 d outputs, one per thread. ---
    {
        const int jj = tid >> 5;     // 0..15
        const int d  = tid & 31;
        const float* x1p = g_x1 + bm * (NN * DD) + d;
        const float* sp  = sS + jj;
        float acc = 0.f;
        #pragma unroll 8
        for (int i = 0; i < NN; i++) acc = fmaf(sp[i * 16], x1p[i * DD], acc);
        const int gj   = j0 + jj;
        const int gidx = bm * (NN * DD) + gj * DD + d;
        out[gidx] = (acc + b3[0] + x[gidx]) * g_mask[bm * NN + gj];
    }
}

// ---------------------------------------------------------------------------
extern "C" void kernel_launch(void* const* d_in, const int* in_sizes, int n_in,
                              void* d_out, int out_size)
{
    (void)in_sizes; (void)n_in; (void)out_size;
    const float* x    = (const float*)d_in[0];
    const float* xsz  = (const float*)d_in[1];
    const float* W1a  = (const float*)d_in[2];
    const float* b1a  = (const float*)d_in[3];
    const float* W1b  = (const float*)d_in[4];
    const float* b1b  = (const float*)d_in[5];
    const float* W2a  = (const float*)d_in[6];
    const float* b2a  = (const float*)d_in[7];
    const float* W2b  = (const float*)d_in[8];
    const float* b2b  = (const float*)d_in[9];
    const float* w3   = (const float*)d_in[10];
    const float* b3   = (const float*)d_in[11];
    float* out = (float*)d_out;

    k1<<<NSET * 8, 256>>>(x, xsz, W1a, b1a, W1b, b1b, W2a);
    k2<<<NSET * 8, 512>>>(x, b2a, W2b, b2b, w3, b3, out);
}